// round 5
// baseline (speedup 1.0000x reference)
#include <cuda_runtime.h>
#include <cuda_fp16.h>

#define C 64
#define MAX_N 50000
#define NPB 96              // nodes per block in k1
#define XR 68               // padded row stride (floats) for xs/wt

// ---------- scratch (device globals; no allocation allowed) ----------
__device__ __half g_h[(size_t)MAX_N * C];  // h = x @ W^T  (fp16: 1 line / node row)
__device__ float  g_si[MAX_N];
__device__ float  g_sj[MAX_N];
__device__ float  g_denom[MAX_N];

// ---------- K0: zero the output (atomics accumulate on top) ----------
__global__ void k0_zero(float4* __restrict__ out, int n4)
{
    int i = blockIdx.x * blockDim.x + threadIdx.x;
    if (i < n4) out[i] = make_float4(0.f, 0.f, 0.f, 0.f);
}

// ---------- K1: h = x W^T, s_i, s_j, denom=0 ----------
// 256 threads. c_slot = t&15 (4 channels), node slot = t>>4 (6 nodes, stride 16).
__global__ void k1_project(const float* __restrict__ x,
                           const float* __restrict__ emb,
                           const float* __restrict__ W,
                           const float* __restrict__ att_i,
                           const float* __restrict__ att_j,
                           const float* __restrict__ att_em_i,
                           const float* __restrict__ att_em_j,
                           int N)
{
    __shared__ float xs[NPB * XR];      // [local node][k]
    __shared__ float wt[C * XR];        // [k][c]  (W transposed)

    int t  = threadIdx.x;
    int nb = blockIdx.x * NPB;

    for (int idx = t; idx < C * C; idx += 256) {
        int c = idx >> 6, k = idx & 63;
        wt[k * XR + c] = W[idx];
    }
    for (int idx = t; idx < NPB * 16; idx += 256) {
        int node = idx >> 4, q = idx & 15;
        int n = nb + node;
        float4 v = (n < N) ? ((const float4*)x)[(size_t)n * 16 + q]
                           : make_float4(0.f, 0.f, 0.f, 0.f);
        *(float4*)&xs[node * XR + q * 4] = v;
    }
    __syncthreads();

    int c_slot = t & 15;
    int slot   = t >> 4;

    float acc[6][4];
#pragma unroll
    for (int i = 0; i < 6; i++)
#pragma unroll
        for (int j = 0; j < 4; j++) acc[i][j] = 0.f;

    const float* wp = &wt[c_slot * 4];
    const float* xp = &xs[slot * XR];

#pragma unroll 4
    for (int k = 0; k < C; k++) {
        float4 w4 = *(const float4*)&wp[k * XR];
#pragma unroll
        for (int i = 0; i < 6; i++) {
            float xk = xp[i * (16 * XR) + k];
            acc[i][0] = fmaf(xk, w4.x, acc[i][0]);
            acc[i][1] = fmaf(xk, w4.y, acc[i][1]);
            acc[i][2] = fmaf(xk, w4.z, acc[i][2]);
            acc[i][3] = fmaf(xk, w4.w, acc[i][3]);
        }
    }

    float4 ai  = ((const float4*)att_i)[c_slot];
    float4 aj  = ((const float4*)att_j)[c_slot];
    float4 aei = ((const float4*)att_em_i)[c_slot];
    float4 aej = ((const float4*)att_em_j)[c_slot];

#pragma unroll
    for (int i = 0; i < 6; i++) {
        int n = nb + slot + 16 * i;
        bool ok = (n < N);
        float4 a = make_float4(acc[i][0], acc[i][1], acc[i][2], acc[i][3]);
        float4 e = ok ? ((const float4*)emb)[(size_t)n * 16 + c_slot]
                      : make_float4(0.f, 0.f, 0.f, 0.f);
        if (ok) {
            __half2 h01 = __floats2half2_rn(a.x, a.y);
            __half2 h23 = __floats2half2_rn(a.z, a.w);
            uint2 pk;
            pk.x = *reinterpret_cast<unsigned*>(&h01);
            pk.y = *reinterpret_cast<unsigned*>(&h23);
            ((uint2*)g_h)[(size_t)n * 16 + c_slot] = pk;
        }

        float pi = a.x*ai.x + a.y*ai.y + a.z*ai.z + a.w*ai.w
                 + e.x*aei.x + e.y*aei.y + e.z*aei.z + e.w*aei.w;
        float pj = a.x*aj.x + a.y*aj.y + a.z*aj.z + a.w*aj.w
                 + e.x*aej.x + e.y*aej.y + e.z*aej.z + e.w*aej.w;
#pragma unroll
        for (int o = 8; o; o >>= 1) {
            pi += __shfl_xor_sync(0xffffffffu, pi, o);
            pj += __shfl_xor_sync(0xffffffffu, pj, o);
        }
        if (ok && c_slot == 0) { g_si[n] = pi; g_sj[n] = pj; }
    }

    if (t < NPB) {
        int n = nb + t;
        if (n < N) g_denom[n] = 0.f;
    }
}

// ---------- K2: fused edge pass (8 lanes/edge, fp16 gather, f32 RED scatter) ----------
__global__ void k2_edge(const int* __restrict__ ei, float* __restrict__ out,
                        int E, int N)
{
    unsigned t = blockIdx.x * blockDim.x + threadIdx.x;
    int e    = (int)(t >> 3);
    int part = (int)(t & 7);
    int lane = threadIdx.x & 31;
    int EN = E + N;
    bool valid = (e < EN);

    int s = 0, d = 0; float ex = 0.f;
    if (valid && part == 0) {
        if (e < E) { s = __ldg(&ei[e]); d = __ldg(&ei[E + e]); }
        else       { s = d = e - E; }
        float a = g_si[d] + g_sj[s];
        a = (a > 0.f) ? a : 0.2f * a;       // leaky_relu, slope 0.2
        ex = __expf(a);                      // softmax shift-invariance: no max pass
        atomicAdd(&g_denom[d], ex);
    }
    int srcl = lane & 24;                    // group leader lane
    s  = __shfl_sync(0xffffffffu, s,  srcl);
    d  = __shfl_sync(0xffffffffu, d,  srcl);
    ex = __shfl_sync(0xffffffffu, ex, srcl);
    if (!valid) return;

    // gather 8 halfs (16B) of h[s]
    uint4 pk = *reinterpret_cast<const uint4*>(&g_h[((size_t)s << 6) + (part << 3)]);
    float2 f0 = __half22float2(*reinterpret_cast<__half2*>(&pk.x));
    float2 f1 = __half22float2(*reinterpret_cast<__half2*>(&pk.y));
    float2 f2 = __half22float2(*reinterpret_cast<__half2*>(&pk.z));
    float2 f3 = __half22float2(*reinterpret_cast<__half2*>(&pk.w));

    float* p = &out[((size_t)d << 6) + (part << 3)];
    asm volatile("red.global.add.v4.f32 [%0], {%1,%2,%3,%4};"
                 :: "l"(p), "f"(f0.x * ex), "f"(f0.y * ex),
                    "f"(f1.x * ex), "f"(f1.y * ex) : "memory");
    asm volatile("red.global.add.v4.f32 [%0], {%1,%2,%3,%4};"
                 :: "l"(p + 4), "f"(f2.x * ex), "f"(f2.y * ex),
                    "f"(f3.x * ex), "f"(f3.y * ex) : "memory");
}

// ---------- K3: normalize by denom, add bias, ReLU (2 float4 per thread) ----------
__global__ void k3_final(float4* __restrict__ out, const float* __restrict__ bias,
                         int N)
{
    int i = blockIdx.x * blockDim.x + threadIdx.x;   // one per 8 channels
    if (i >= N * 8) return;
    int n = i >> 3, q = i & 7;
    float r = 1.f / (g_denom[n] + 1e-16f);
    float4 b0 = ((const float4*)bias)[q * 2];
    float4 b1 = ((const float4*)bias)[q * 2 + 1];
    float4 v0 = out[n * 16 + q * 2];
    float4 v1 = out[n * 16 + q * 2 + 1];
    v0.x = fmaxf(fmaf(v0.x, r, b0.x), 0.f);
    v0.y = fmaxf(fmaf(v0.y, r, b0.y), 0.f);
    v0.z = fmaxf(fmaf(v0.z, r, b0.z), 0.f);
    v0.w = fmaxf(fmaf(v0.w, r, b0.w), 0.f);
    v1.x = fmaxf(fmaf(v1.x, r, b1.x), 0.f);
    v1.y = fmaxf(fmaf(v1.y, r, b1.y), 0.f);
    v1.z = fmaxf(fmaf(v1.z, r, b1.z), 0.f);
    v1.w = fmaxf(fmaf(v1.w, r, b1.w), 0.f);
    out[n * 16 + q * 2]     = v0;
    out[n * 16 + q * 2 + 1] = v1;
}

extern "C" void kernel_launch(void* const* d_in, const int* in_sizes, int n_in,
                              void* d_out, int out_size)
{
    const float* x        = (const float*)d_in[0];
    const int*   ei       = (const int*)  d_in[1];
    const float* emb      = (const float*)d_in[2];
    const float* W        = (const float*)d_in[3];
    const float* att_i    = (const float*)d_in[4];
    const float* att_j    = (const float*)d_in[5];
    const float* att_em_i = (const float*)d_in[6];
    const float* att_em_j = (const float*)d_in[7];
    const float* bias     = (const float*)d_in[8];
    float* out = (float*)d_out;

    int N  = in_sizes[0] / C;
    int E  = in_sizes[1] / 2;
    int EN = E + N;

    int n4 = out_size / 4;
    k0_zero<<<(n4 + 255) / 256, 256>>>((float4*)out, n4);
    k1_project<<<(N + NPB - 1) / NPB, 256>>>(x, emb, W, att_i, att_j,
                                             att_em_i, att_em_j, N);
    unsigned t2 = (unsigned)EN * 8u;
    k2_edge<<<(t2 + 255) / 256, 256>>>(ei, out, E, N);
    k3_final<<<(N * 8 + 255) / 256, 256>>>((float4*)out, bias, N);
}

// round 6
// speedup vs baseline: 1.1153x; 1.1153x over previous
#include <cuda_runtime.h>
#include <cuda_fp16.h>

#define C 64
#define MAX_N 50000
#define NPB 96              // nodes per block in k1
#define XR 68               // padded row stride (floats) for xs/wt

// ---------- scratch (device globals; no allocation allowed) ----------
__device__ __half g_h[(size_t)MAX_N * C];  // h = x @ W^T (fp16: node row = 1 L2 line)
__device__ float  g_si[MAX_N];
__device__ float  g_sj[MAX_N];
__device__ float  g_denom[MAX_N];

// ---------- K0: zero the output (atomics accumulate on top) ----------
__global__ void k0_zero(float4* __restrict__ out, int n4)
{
    int i = blockIdx.x * blockDim.x + threadIdx.x;
    if (i < n4) out[i] = make_float4(0.f, 0.f, 0.f, 0.f);
}

// ---------- K1: h = x W^T, s_i, s_j, denom=0 ----------
__global__ void k1_project(const float* __restrict__ x,
                           const float* __restrict__ emb,
                           const float* __restrict__ W,
                           const float* __restrict__ att_i,
                           const float* __restrict__ att_j,
                           const float* __restrict__ att_em_i,
                           const float* __restrict__ att_em_j,
                           int N)
{
    __shared__ float xs[NPB * XR];      // [local node][k]
    __shared__ float wt[C * XR];        // [k][c]  (W transposed)

    int t  = threadIdx.x;
    int nb = blockIdx.x * NPB;

    for (int idx = t; idx < C * C; idx += 256) {
        int c = idx >> 6, k = idx & 63;
        wt[k * XR + c] = W[idx];
    }
    for (int idx = t; idx < NPB * 16; idx += 256) {
        int node = idx >> 4, q = idx & 15;
        int n = nb + node;
        float4 v = (n < N) ? ((const float4*)x)[(size_t)n * 16 + q]
                           : make_float4(0.f, 0.f, 0.f, 0.f);
        *(float4*)&xs[node * XR + q * 4] = v;
    }
    __syncthreads();

    int c_slot = t & 15;
    int slot   = t >> 4;

    float acc[6][4];
#pragma unroll
    for (int i = 0; i < 6; i++)
#pragma unroll
        for (int j = 0; j < 4; j++) acc[i][j] = 0.f;

    const float* wp = &wt[c_slot * 4];
    const float* xp = &xs[slot * XR];

#pragma unroll 4
    for (int k = 0; k < C; k++) {
        float4 w4 = *(const float4*)&wp[k * XR];
#pragma unroll
        for (int i = 0; i < 6; i++) {
            float xk = xp[i * (16 * XR) + k];
            acc[i][0] = fmaf(xk, w4.x, acc[i][0]);
            acc[i][1] = fmaf(xk, w4.y, acc[i][1]);
            acc[i][2] = fmaf(xk, w4.z, acc[i][2]);
            acc[i][3] = fmaf(xk, w4.w, acc[i][3]);
        }
    }

    float4 ai  = ((const float4*)att_i)[c_slot];
    float4 aj  = ((const float4*)att_j)[c_slot];
    float4 aei = ((const float4*)att_em_i)[c_slot];
    float4 aej = ((const float4*)att_em_j)[c_slot];

#pragma unroll
    for (int i = 0; i < 6; i++) {
        int n = nb + slot + 16 * i;
        bool ok = (n < N);
        float4 a = make_float4(acc[i][0], acc[i][1], acc[i][2], acc[i][3]);
        float4 e = ok ? ((const float4*)emb)[(size_t)n * 16 + c_slot]
                      : make_float4(0.f, 0.f, 0.f, 0.f);
        if (ok) {
            __half2 h01 = __floats2half2_rn(a.x, a.y);
            __half2 h23 = __floats2half2_rn(a.z, a.w);
            uint2 pk;
            pk.x = *reinterpret_cast<unsigned*>(&h01);
            pk.y = *reinterpret_cast<unsigned*>(&h23);
            ((uint2*)g_h)[(size_t)n * 16 + c_slot] = pk;
        }

        float pi = a.x*ai.x + a.y*ai.y + a.z*ai.z + a.w*ai.w
                 + e.x*aei.x + e.y*aei.y + e.z*aei.z + e.w*aei.w;
        float pj = a.x*aj.x + a.y*aj.y + a.z*aj.z + a.w*aj.w
                 + e.x*aej.x + e.y*aej.y + e.z*aej.z + e.w*aej.w;
#pragma unroll
        for (int o = 8; o; o >>= 1) {
            pi += __shfl_xor_sync(0xffffffffu, pi, o);
            pj += __shfl_xor_sync(0xffffffffu, pj, o);
        }
        if (ok && c_slot == 0) { g_si[n] = pi; g_sj[n] = pj; }
    }

    if (t < NPB) {
        int n = nb + t;
        if (n < N) g_denom[n] = 0.f;
    }
}

// ---------- K2: fused edge pass (16 lanes/edge, 8B fp16 gather, one RED.v4/lane) ----------
__global__ void k2_edge(const int* __restrict__ ei, float* __restrict__ out,
                        int E, int N)
{
    unsigned t = blockIdx.x * blockDim.x + threadIdx.x;
    int e    = (int)(t >> 4);
    int part = (int)(t & 15);
    int lane = threadIdx.x & 31;
    int EN = E + N;
    bool valid = (e < EN);

    int s = 0, d = 0; float ex = 0.f;
    if (valid && part == 0) {
        if (e < E) { s = __ldg(&ei[e]); d = __ldg(&ei[E + e]); }
        else       { s = d = e - E; }
        float a = g_si[d] + g_sj[s];
        a = (a > 0.f) ? a : 0.2f * a;       // leaky_relu, slope 0.2
        ex = __expf(a);                      // softmax shift-invariance: no max pass
        atomicAdd(&g_denom[d], ex);
    }
    int srcl = lane & 16;
    s  = __shfl_sync(0xffffffffu, s,  srcl);
    d  = __shfl_sync(0xffffffffu, d,  srcl);
    ex = __shfl_sync(0xffffffffu, ex, srcl);
    if (!valid) return;

    // gather 4 halfs (8B) of h[s] for this lane's 4 channels
    uint2 pk = *reinterpret_cast<const uint2*>(&g_h[((size_t)s << 6) + (part << 2)]);
    float2 f0 = __half22float2(*reinterpret_cast<__half2*>(&pk.x));
    float2 f1 = __half22float2(*reinterpret_cast<__half2*>(&pk.y));

    float* p = &out[((size_t)d << 6) + (part << 2)];
    asm volatile("red.global.add.v4.f32 [%0], {%1,%2,%3,%4};"
                 :: "l"(p), "f"(f0.x * ex), "f"(f0.y * ex),
                    "f"(f1.x * ex), "f"(f1.y * ex) : "memory");
}

// ---------- K3: normalize by denom, add bias, ReLU ----------
__global__ void k3_final(float4* __restrict__ out, const float* __restrict__ bias,
                         int N)
{
    int i = blockIdx.x * blockDim.x + threadIdx.x;
    if (i >= N * 16) return;
    int n = i >> 4, q = i & 15;
    float4 v = out[i];
    float r = 1.f / (g_denom[n] + 1e-16f);
    float4 b = ((const float4*)bias)[q];
    v.x = fmaxf(fmaf(v.x, r, b.x), 0.f);
    v.y = fmaxf(fmaf(v.y, r, b.y), 0.f);
    v.z = fmaxf(fmaf(v.z, r, b.z), 0.f);
    v.w = fmaxf(fmaf(v.w, r, b.w), 0.f);
    out[i] = v;
}

extern "C" void kernel_launch(void* const* d_in, const int* in_sizes, int n_in,
                              void* d_out, int out_size)
{
    const float* x        = (const float*)d_in[0];
    const int*   ei       = (const int*)  d_in[1];
    const float* emb      = (const float*)d_in[2];
    const float* W        = (const float*)d_in[3];
    const float* att_i    = (const float*)d_in[4];
    const float* att_j    = (const float*)d_in[5];
    const float* att_em_i = (const float*)d_in[6];
    const float* att_em_j = (const float*)d_in[7];
    const float* bias     = (const float*)d_in[8];
    float* out = (float*)d_out;

    int N  = in_sizes[0] / C;
    int E  = in_sizes[1] / 2;
    int EN = E + N;

    int n4 = out_size / 4;
    k0_zero<<<(n4 + 255) / 256, 256>>>((float4*)out, n4);
    k1_project<<<(N + NPB - 1) / NPB, 256>>>(x, emb, W, att_i, att_j,
                                             att_em_i, att_em_j, N);
    unsigned t2 = (unsigned)EN * 16u;
    k2_edge<<<(t2 + 255) / 256, 256>>>(ei, out, E, N);
    k3_final<<<(N * 16 + 255) / 256, 256>>>((float4*)out, bias, N);
}